// round 9
// baseline (speedup 1.0000x reference)
#include <cuda_runtime.h>

// BEVFeatureExtractorV2 — R9: 8 channel passes, 2 points per warp (double MLP).
// feats: (B=4, C=256, H=256, W=256) fp32   rois: (B=4, N=512, 7) fp32
// out: (B, N, 5*C) fp32
//
// Traffic is at the unique-sector floor (~221MB); rate ~5.7TB/s. R9 raises
// per-warp memory-level parallelism: geometry A -> issue A loads -> geometry B
// -> issue B loads -> consume. 4 LDG.128 in flight per warp instead of 2.

#define BB 4
#define NN 512
#define CC 256
#define HH 256
#define WW 256
#define NPTS 5
#define HWSZ (HH * WW)
#define NPOINTS (BB * NN * NPTS)    // 10240
#define PASSES 8
#define CQ (CC / PASSES)            // 32 channels per pass (1 per lane)
#define WARPS_PER_BLOCK 4
#define PTS_PER_WARP 2
#define PT_BLOCKS (NPOINTS / (WARPS_PER_BLOCK * PTS_PER_WARP))   // 1280 per pass

__device__ __forceinline__ float f4_get(const float4& v, int i) {
    return (i == 0) ? v.x : (i == 1) ? v.y : (i == 2) ? v.z : v.w;
}

__device__ __forceinline__ void stcs(float* p, float v) {
    asm volatile("st.global.cs.f32 [%0], %1;" :: "l"(p), "f"(v));
}

struct PointGeom {
    float wa, wb, wc, wd;
    int r0, r1;       // row base offsets (quad-aligned)
    int off0, off1;   // 0..3 ; off1 > 3 => x1 in next quad
    int o01;          // scalar offset of (y0, x1) for cross-quad case
};

__device__ __forceinline__ PointGeom make_geom(const float* __restrict__ rois,
                                               int b, int local)
{
    const int p = local % NPTS;
    const int n = local / NPTS;

    const float* roi = rois + (b * NN + n) * 7;
    const float cx = roi[0];
    const float cy = roi[1];
    const float dx = roi[3];
    const float dy = roi[4];
    const float ry = roi[6];

    float sn, cs;
    sincosf(ry, &sn, &cs);

    // rot(x, y) = (x*cos + y*sin, -x*sin + y*cos)  (row-vector * R)
    float px = cx, py = cy;
    const float hx = 0.5f * dx, hy = 0.5f * dy;
    if (p == 1)      { px = cx - hx * cs; py = cy + hx * sn; }
    else if (p == 2) { px = cx + hx * cs; py = cy - hx * sn; }
    else if (p == 3) { px = cx - hy * sn; py = cy - hy * cs; }
    else if (p == 4) { px = cx + hy * sn; py = cy + hy * cs; }

    const float x = (px + 51.2f) / 0.1f / 4.0f;
    const float y = (py + 51.2f) / 0.1f / 4.0f;

    const float xf = floorf(x);
    const float yf = floorf(y);
    int x0 = (int)xf,  x1 = (int)xf + 1;
    int y0 = (int)yf,  y1 = (int)yf + 1;
    x0 = min(max(x0, 0), WW - 1);
    x1 = min(max(x1, 0), WW - 1);
    y0 = min(max(y0, 0), HH - 1);
    y1 = min(max(y1, 0), HH - 1);

    const float x0f = (float)x0, x1f = (float)x1;
    const float y0f = (float)y0, y1f = (float)y1;

    PointGeom g;
    g.wa = (x1f - x) * (y1f - y);
    g.wb = (x1f - x) * (y - y0f);
    g.wc = (x - x0f) * (y1f - y);
    g.wd = (x - x0f) * (y - y0f);

    const int q = x0 & ~3;
    g.off0 = x0 - q;
    g.off1 = x1 - q;
    g.r0 = y0 * WW + q;
    g.r1 = y1 * WW + q;
    g.o01 = y0 * WW + x1;
    return g;
}

__device__ __forceinline__ float sample(const PointGeom& g,
                                        const float4& v0, const float4& v1,
                                        const float* __restrict__ f)
{
    if (g.off1 <= 3) {   // warp-uniform
        const float ia = f4_get(v0, g.off0);
        const float ic = f4_get(v0, g.off1);
        const float ib = f4_get(v1, g.off0);
        const float id = f4_get(v1, g.off1);
        return g.wa * ia + g.wb * ib + g.wc * ic + g.wd * id;
    } else {
        const float ic = __ldg(f + g.o01);
        const float id = __ldg(f + g.o01 + (g.r1 - g.r0));
        return g.wa * v0.w + g.wb * v1.w + g.wc * ic + g.wd * id;
    }
}

__global__ __launch_bounds__(32 * WARPS_PER_BLOCK, 12) void bev_extract_kernel(
    const float* __restrict__ feats,
    const float* __restrict__ rois,
    float* __restrict__ out)
{
    const int pass  = blockIdx.x / PT_BLOCKS;            // slow dim: 8 passes
    const int pblk  = blockIdx.x % PT_BLOCKS;
    const int warp  = threadIdx.x >> 5;
    const int lane  = threadIdx.x & 31;

    const int base_pt = (pblk * WARPS_PER_BLOCK + warp) * PTS_PER_WARP;
    const int b = base_pt / (NN * NPTS);
    const int localA = base_pt;
    const int localB = base_pt + 1;      // same batch (points per batch even)

    const float* __restrict__ fbase = feats + (size_t)b * CC * HWSZ;
    const int c = pass * CQ + lane;
    const float* __restrict__ f = fbase + c * HWSZ;

    // Geometry A, issue A loads.
    const PointGeom ga = make_geom(rois, b, localA % (NN * NPTS));
    const float4 va0 = __ldg((const float4*)(f + ga.r0));
    const float4 va1 = __ldg((const float4*)(f + ga.r1));

    // Geometry B, issue B loads (A loads still in flight).
    const PointGeom gb = make_geom(rois, b, localB % (NN * NPTS));
    const float4 vb0 = __ldg((const float4*)(f + gb.r0));
    const float4 vb1 = __ldg((const float4*)(f + gb.r1));

    const float ra = sample(ga, va0, va1, f);
    const float rb = sample(gb, vb0, vb1, f);

    stcs(out + (size_t)localA * CC + c, ra);
    stcs(out + (size_t)localB * CC + c, rb);
}

extern "C" void kernel_launch(void* const* d_in, const int* in_sizes, int n_in,
                              void* d_out, int out_size)
{
    const float* feats = (const float*)d_in[0];
    const float* rois  = (const float*)d_in[1];
    float* out = (float*)d_out;

    const int blocks = PASSES * PT_BLOCKS;   // 8 * 1280 = 10240
    bev_extract_kernel<<<blocks, 32 * WARPS_PER_BLOCK>>>(feats, rois, out);
}

// round 10
// speedup vs baseline: 1.0519x; 1.0519x over previous
#include <cuda_runtime.h>

// BEVFeatureExtractorV2 — R10 (final): R7 schedule + micro-trimmed prologue.
// feats: (B=4, C=256, H=256, W=256) fp32   rois: (B=4, N=512, 7) fp32
// out: (B, N, 5*C) fp32
//
// Established across R1-R9: traffic is compulsory (~221MB = unique 64B read
// sectors + 10.5MB coalesced writes); DRAM rate for this scatter pattern is
// ceiling-limited at ~5.7TB/s (independent of occupancy, request ordering,
// prefetch, and per-warp MLP). Floor ~38.5us kernel. Design: 8 channel passes
// as the slow grid dim (32MB L2-resident footprint per pass -> every sector
// fetched exactly once), one (point, channel) pair per lane via quad-aligned
// LDG.128 taps (warp-uniform cross-quad fallback), streaming output stores.

#define BB 4
#define NN 512
#define CC 256
#define HH 256
#define WW 256
#define NPTS 5
#define HWSZ (HH * WW)
#define NPOINTS (BB * NN * NPTS)    // 10240
#define PASSES 8
#define CQ (CC / PASSES)            // 32 channels per pass (1 per lane)
#define WARPS_PER_BLOCK 4
#define PT_BLOCKS (NPOINTS / WARPS_PER_BLOCK)   // 2560 blocks per pass

__device__ __forceinline__ float f4_get(const float4& v, int i) {
    return (i == 0) ? v.x : (i == 1) ? v.y : (i == 2) ? v.z : v.w;
}

__device__ __forceinline__ void stcs(float* p, float v) {
    asm volatile("st.global.cs.f32 [%0], %1;" :: "l"(p), "f"(v));
}

__global__ __launch_bounds__(32 * WARPS_PER_BLOCK, 14) void bev_extract_kernel(
    const float* __restrict__ feats,
    const float* __restrict__ rois,
    float* __restrict__ out)
{
    const int pass  = blockIdx.x / PT_BLOCKS;            // slow dim: 8 passes
    const int pblk  = blockIdx.x % PT_BLOCKS;
    const int warp  = threadIdx.x >> 5;
    const int lane  = threadIdx.x & 31;
    const int point = pblk * WARPS_PER_BLOCK + warp;     // 0..NPOINTS-1

    const int p = point % NPTS;
    const int nb = point / NPTS;                         // b*NN + n

    const float* __restrict__ roi = rois + nb * 7;
    const float cx = roi[0];
    const float cy = roi[1];
    const float dx = roi[3];
    const float dy = roi[4];
    const float ry = roi[6];
    const int b = nb >> 9;                               // NN == 512

    // ry in [-pi, pi]: fast-path sincos is exact enough (<1e-5 px error).
    float sn, cs;
    __sincosf(ry, &sn, &cs);

    // rot(x, y) = (x*cos + y*sin, -x*sin + y*cos)  (row-vector * R)
    float px = cx, py = cy;
    const float hx = 0.5f * dx, hy = 0.5f * dy;
    if (p == 1)      { px = cx - hx * cs; py = cy + hx * sn; }
    else if (p == 2) { px = cx + hx * cs; py = cy - hx * sn; }
    else if (p == 3) { px = cx - hy * sn; py = cy - hy * cs; }
    else if (p == 4) { px = cx + hy * sn; py = cy + hy * cs; }

    const float x = (px + 51.2f) / 0.1f / 4.0f;
    const float y = (py + 51.2f) / 0.1f / 4.0f;

    const float xf = floorf(x);
    const float yf = floorf(y);
    int x0 = (int)xf,  x1 = (int)xf + 1;
    int y0 = (int)yf,  y1 = (int)yf + 1;
    x0 = min(max(x0, 0), WW - 1);
    x1 = min(max(x1, 0), WW - 1);
    y0 = min(max(y0, 0), HH - 1);
    y1 = min(max(y1, 0), HH - 1);

    const float x0f = (float)x0, x1f = (float)x1;
    const float y0f = (float)y0, y1f = (float)y1;
    const float wa = (x1f - x) * (y1f - y);   // (y0, x0)
    const float wb = (x1f - x) * (y - y0f);   // (y1, x0)
    const float wc = (x - x0f) * (y1f - y);   // (y0, x1)
    const float wd = (x - x0f) * (y - y0f);   // (y1, x1)

    const int q    = x0 & ~3;
    const int off0 = x0 - q;            // 0..3
    const int off1 = x1 - q;            // >3 => x1 outside quad
    const bool in_quad = (off1 <= 3);   // warp-uniform

    const int r0 = y0 * WW + q;
    const int r1 = y1 * WW + q;

    const int c = pass * CQ + lane;     // CQ == 32: one channel per lane
    const float* __restrict__ f = feats + ((size_t)b * CC + c) * HWSZ;
    float* __restrict__ op = out + (size_t)point * CC + c;

    if (in_quad) {
        const float4 v0 = __ldg((const float4*)(f + r0));
        const float4 v1 = __ldg((const float4*)(f + r1));
        const float ia = f4_get(v0, off0);
        const float ic = f4_get(v0, off1);
        const float ib = f4_get(v1, off0);
        const float id = f4_get(v1, off1);
        stcs(op, wa * ia + wb * ib + wc * ic + wd * id);
    } else {
        // off0 == 3, x1 in next quad: scalar taps for x1.
        const int o01 = y0 * WW + x1;
        const int o11 = y1 * WW + x1;
        const float4 v0 = __ldg((const float4*)(f + r0));
        const float4 v1 = __ldg((const float4*)(f + r1));
        const float ic = __ldg(f + o01);
        const float id = __ldg(f + o11);
        stcs(op, wa * v0.w + wb * v1.w + wc * ic + wd * id);
    }
}

extern "C" void kernel_launch(void* const* d_in, const int* in_sizes, int n_in,
                              void* d_out, int out_size)
{
    const float* feats = (const float*)d_in[0];
    const float* rois  = (const float*)d_in[1];
    float* out = (float*)d_out;

    const int blocks = PASSES * PT_BLOCKS;   // 8 * 2560 = 20480
    bev_extract_kernel<<<blocks, 32 * WARPS_PER_BLOCK>>>(feats, rois, out);
}

// round 11
// speedup vs baseline: 1.0528x; 1.0008x over previous
#include <cuda_runtime.h>

// BEVFeatureExtractorV2 — FINAL (R11 = R10 + const-fold): channel-pass schedule.
// feats: (B=4, C=256, H=256, W=256) fp32   rois: (B=4, N=512, 7) fp32
// out: (B, N, 5*C) fp32
//
// Converged model (R1-R10): traffic is compulsory (~220MB = unique 64B read
// sectors + 10.5MB coalesced writes); DRAM rate for this scatter pattern is
// ceiling-limited at ~5.7TB/s (invariant to occupancy, request order, prefetch,
// and per-warp MLP — each tested). Floor ~39us. Design: 8 channel passes as the
// slow grid dim (32MB L2-resident footprint per pass -> each sector fetched
// once), one (point, channel) per lane via quad-aligned LDG.128 taps with a
// warp-uniform cross-quad fallback, fast sincos, streaming output stores.

#define BB 4
#define NN 512
#define CC 256
#define HH 256
#define WW 256
#define NPTS 5
#define HWSZ (HH * WW)
#define NPOINTS (BB * NN * NPTS)    // 10240
#define PASSES 8
#define CQ (CC / PASSES)            // 32 channels per pass (1 per lane)
#define WARPS_PER_BLOCK 4
#define PT_BLOCKS (NPOINTS / WARPS_PER_BLOCK)   // 2560 blocks per pass

__device__ __forceinline__ float f4_get(const float4& v, int i) {
    return (i == 0) ? v.x : (i == 1) ? v.y : (i == 2) ? v.z : v.w;
}

__device__ __forceinline__ void stcs(float* p, float v) {
    asm volatile("st.global.cs.f32 [%0], %1;" :: "l"(p), "f"(v));
}

__global__ __launch_bounds__(32 * WARPS_PER_BLOCK, 14) void bev_extract_kernel(
    const float* __restrict__ feats,
    const float* __restrict__ rois,
    float* __restrict__ out)
{
    const int pass  = blockIdx.x / PT_BLOCKS;            // slow dim: 8 passes
    const int pblk  = blockIdx.x % PT_BLOCKS;
    const int warp  = threadIdx.x >> 5;
    const int lane  = threadIdx.x & 31;
    const int point = pblk * WARPS_PER_BLOCK + warp;     // 0..NPOINTS-1

    const int p  = point % NPTS;
    const int nb = point / NPTS;                         // b*NN + n

    const float* __restrict__ roi = rois + nb * 7;
    const float cx = roi[0];
    const float cy = roi[1];
    const float dx = roi[3];
    const float dy = roi[4];
    const float ry = roi[6];
    const int b = nb >> 9;                               // NN == 512

    // ry in [-pi, pi]: fast-path sincos is exact enough (<1e-5 px error).
    float sn, cs;
    __sincosf(ry, &sn, &cs);

    // rot(x, y) = (x*cos + y*sin, -x*sin + y*cos)  (row-vector * R)
    float px = cx, py = cy;
    const float hx = 0.5f * dx, hy = 0.5f * dy;
    if (p == 1)      { px = cx - hx * cs; py = cy + hx * sn; }
    else if (p == 2) { px = cx + hx * cs; py = cy - hx * sn; }
    else if (p == 3) { px = cx - hy * sn; py = cy - hy * cs; }
    else if (p == 4) { px = cx + hy * sn; py = cy + hy * cs; }

    // world -> pixel: (p + 51.2) / 0.1 / 4  ==  (p + 51.2) * 2.5
    const float x = (px + 51.2f) * 2.5f;
    const float y = (py + 51.2f) * 2.5f;

    const float xf = floorf(x);
    const float yf = floorf(y);
    int x0 = (int)xf,  x1 = (int)xf + 1;
    int y0 = (int)yf,  y1 = (int)yf + 1;
    x0 = min(max(x0, 0), WW - 1);
    x1 = min(max(x1, 0), WW - 1);
    y0 = min(max(y0, 0), HH - 1);
    y1 = min(max(y1, 0), HH - 1);

    const float x0f = (float)x0, x1f = (float)x1;
    const float y0f = (float)y0, y1f = (float)y1;
    const float wa = (x1f - x) * (y1f - y);   // (y0, x0)
    const float wb = (x1f - x) * (y - y0f);   // (y1, x0)
    const float wc = (x - x0f) * (y1f - y);   // (y0, x1)
    const float wd = (x - x0f) * (y - y0f);   // (y1, x1)

    const int q    = x0 & ~3;
    const int off0 = x0 - q;            // 0..3
    const int off1 = x1 - q;            // >3 => x1 outside quad
    const bool in_quad = (off1 <= 3);   // warp-uniform

    const int r0 = y0 * WW + q;
    const int r1 = y1 * WW + q;

    const int c = pass * CQ + lane;     // CQ == 32: one channel per lane
    const float* __restrict__ f = feats + ((size_t)b * CC + c) * HWSZ;
    float* __restrict__ op = out + (size_t)point * CC + c;

    if (in_quad) {
        const float4 v0 = __ldg((const float4*)(f + r0));
        const float4 v1 = __ldg((const float4*)(f + r1));
        const float ia = f4_get(v0, off0);
        const float ic = f4_get(v0, off1);
        const float ib = f4_get(v1, off0);
        const float id = f4_get(v1, off1);
        stcs(op, wa * ia + wb * ib + wc * ic + wd * id);
    } else {
        // off0 == 3, x1 in next quad: scalar taps for x1.
        const int o01 = y0 * WW + x1;
        const int o11 = y1 * WW + x1;
        const float4 v0 = __ldg((const float4*)(f + r0));
        const float4 v1 = __ldg((const float4*)(f + r1));
        const float ic = __ldg(f + o01);
        const float id = __ldg(f + o11);
        stcs(op, wa * v0.w + wb * v1.w + wc * ic + wd * id);
    }
}

extern "C" void kernel_launch(void* const* d_in, const int* in_sizes, int n_in,
                              void* d_out, int out_size)
{
    const float* feats = (const float*)d_in[0];
    const float* rois  = (const float*)d_in[1];
    float* out = (float*)d_out;

    const int blocks = PASSES * PT_BLOCKS;   // 8 * 2560 = 20480
    bev_extract_kernel<<<blocks, 32 * WARPS_PER_BLOCK>>>(feats, rois, out);
}